// round 9
// baseline (speedup 1.0000x reference)
#include <cuda_runtime.h>
#include <stdint.h>

#define FULL 0xffffffffu

constexpr int Bb = 8;
constexpr int Nn = 16384;
constexpr int Gg = 257;
constexpr int Kk = 32;
constexpr int NCH = 64;                 // chunks per batch (256 pts each)
constexpr float LBMARGIN = 1e-3f;       // >> any float slop in lb vs d2 model

// Sphere-grid centers.
__device__ float g_cx[Gg];
__device__ float g_cy[Gg];
__device__ float g_cz[Gg];

// Morton-sorted cloud scratch (SoA) + orig indices + chunk AABBs.
__device__ float g_px[Bb * Nn];
__device__ float g_py[Bb * Nn];
__device__ float g_pz[Bb * Nn];
__device__ unsigned short g_pidx[Bb * Nn];
__device__ float g_aabb[Bb * NCH * 8];  // xlo,xhi,ylo,yhi,zlo,zhi,pad,pad

__global__ void init_centers_kernel() {
    __shared__ int pf[736];
    int t = threadIdx.x;
    int keep = 0;
    float x = 0.f, y = 0.f, z = 0.f;
    if (t < 729) {
        int i = t / 81, j = (t / 9) % 9, k = t % 9;
        x = 0.25f * (float)i - 1.0f;
        y = 0.25f * (float)j - 1.0f;
        z = 0.25f * (float)k - 1.0f;
        float n2 = x * x + y * y + z * z;
        keep = (n2 <= 1.00001f) ? 1 : 0;
    }
    pf[t] = keep;
    __syncthreads();
    for (int s = 1; s < 736; s <<= 1) {
        int v = (t >= s) ? pf[t - s] : 0;
        __syncthreads();
        pf[t] += v;
        __syncthreads();
    }
    if (keep) {
        int p = pf[t] - 1;
        g_cx[p] = x; g_cy[p] = y; g_cz[p] = z;
    }
}

__device__ __forceinline__ unsigned spread4(unsigned v) {
    v = (v | (v << 4)) & 0x0C3u;
    v = (v | (v << 2)) & 0x249u;
    return v;
}
__device__ __forceinline__ unsigned morton12(float x, float y, float z) {
    int qx = min(15, max(0, (int)((x + 3.0f) * (16.0f / 6.0f))));
    int qy = min(15, max(0, (int)((y + 3.0f) * (16.0f / 6.0f))));
    int qz = min(15, max(0, (int)((z + 3.0f) * (16.0f / 6.0f))));
    return spread4((unsigned)qx) | (spread4((unsigned)qy) << 1)
         | (spread4((unsigned)qz) << 2);
}

// One block per batch: Morton counting-sort into scratch SoA + chunk AABBs.
__global__ __launch_bounds__(1024, 1)
void morton_sort_kernel(const float* __restrict__ xyz) {
    __shared__ unsigned hist[4096];
    __shared__ unsigned sb[1024];
    const int b = blockIdx.x;
    const int t = threadIdx.x;
    const float* src = xyz + (size_t)b * Nn * 3;

    for (int i = t; i < 4096; i += 1024) hist[i] = 0;
    __syncthreads();

    unsigned keys[16];
    #pragma unroll
    for (int k = 0; k < 16; ++k) {
        const int p = t + 1024 * k;
        const float x = src[3 * p + 0];
        const float y = src[3 * p + 1];
        const float z = src[3 * p + 2];
        const unsigned key = morton12(x, y, z);
        keys[k] = key;
        atomicAdd(&hist[key], 1u);
    }
    __syncthreads();

    // Exclusive scan of 4096 bins (4 per thread + block scan of totals).
    const unsigned a0 = hist[4 * t], a1 = hist[4 * t + 1];
    const unsigned a2 = hist[4 * t + 2], a3 = hist[4 * t + 3];
    const unsigned tot = a0 + a1 + a2 + a3;
    sb[t] = tot;
    __syncthreads();
    for (int s = 1; s < 1024; s <<= 1) {
        const unsigned v = (t >= s) ? sb[t - s] : 0u;
        __syncthreads();
        sb[t] += v;
        __syncthreads();
    }
    const unsigned excl = sb[t] - tot;
    hist[4 * t]     = excl;
    hist[4 * t + 1] = excl + a0;
    hist[4 * t + 2] = excl + a0 + a1;
    hist[4 * t + 3] = excl + a0 + a1 + a2;
    __syncthreads();

    // Scatter (intra-bin order nondeterministic; output-invariant).
    #pragma unroll
    for (int k = 0; k < 16; ++k) {
        const int p = t + 1024 * k;
        const float x = src[3 * p + 0];
        const float y = src[3 * p + 1];
        const float z = src[3 * p + 2];
        const unsigned pos = atomicAdd(&hist[keys[k]], 1u);
        g_px[b * Nn + pos] = x;
        g_py[b * Nn + pos] = y;
        g_pz[b * Nn + pos] = z;
        g_pidx[b * Nn + pos] = (unsigned short)p;
    }
    __syncthreads();   // block-level fence: scatter visible to AABB phase

    // Chunk AABBs: warp w handles chunks 2w, 2w+1 (8 points per lane).
    const int wid = t >> 5, lane = t & 31;
    for (int c = 2 * wid; c < 2 * wid + 2; ++c) {
        float xlo = 1e30f, xhi = -1e30f;
        float ylo = 1e30f, yhi = -1e30f;
        float zlo = 1e30f, zhi = -1e30f;
        #pragma unroll
        for (int k = 0; k < 8; ++k) {
            const int p = b * Nn + c * 256 + lane + 32 * k;
            const float x = g_px[p], y = g_py[p], z = g_pz[p];
            xlo = fminf(xlo, x); xhi = fmaxf(xhi, x);
            ylo = fminf(ylo, y); yhi = fmaxf(yhi, y);
            zlo = fminf(zlo, z); zhi = fmaxf(zhi, z);
        }
        #pragma unroll
        for (int o = 16; o >= 1; o >>= 1) {
            xlo = fminf(xlo, __shfl_xor_sync(FULL, xlo, o));
            xhi = fmaxf(xhi, __shfl_xor_sync(FULL, xhi, o));
            ylo = fminf(ylo, __shfl_xor_sync(FULL, ylo, o));
            yhi = fmaxf(yhi, __shfl_xor_sync(FULL, yhi, o));
            zlo = fminf(zlo, __shfl_xor_sync(FULL, zlo, o));
            zhi = fmaxf(zhi, __shfl_xor_sync(FULL, zhi, o));
        }
        if (lane == 0) {
            float* d = g_aabb + (b * NCH + c) * 8;
            d[0] = xlo; d[1] = xhi; d[2] = ylo;
            d[3] = yhi; d[4] = zlo; d[5] = zhi;
        }
    }
}

// ---- packed f32x2 exact helpers ----
__device__ __forceinline__ uint64_t f2fma(uint64_t a, uint64_t b, uint64_t c) {
    uint64_t d; asm("fma.rn.f32x2 %0, %1, %2, %3;" : "=l"(d) : "l"(a), "l"(b), "l"(c));
    return d;
}
__device__ __forceinline__ uint64_t f2mul(uint64_t a, uint64_t b) {
    uint64_t d; asm("mul.rn.f32x2 %0, %1, %2;" : "=l"(d) : "l"(a), "l"(b));
    return d;
}
__device__ __forceinline__ uint64_t f2add(uint64_t a, uint64_t b) {
    uint64_t d; asm("add.rn.f32x2 %0, %1, %2;" : "=l"(d) : "l"(a), "l"(b));
    return d;
}
__device__ __forceinline__ uint64_t f2pack(float lo, float hi) {
    uint64_t d; asm("mov.b64 %0, {%1, %2};" : "=l"(d) : "f"(lo), "f"(hi));
    return d;
}
__device__ __forceinline__ void f2unpack(uint64_t v, float& lo, float& hi) {
    asm("mov.b64 {%0, %1}, %2;" : "=f"(lo), "=f"(hi) : "l"(v));
}
__device__ __forceinline__ unsigned long long ull_min(unsigned long long a,
                                                      unsigned long long b) {
    return a < b ? a : b;
}
__device__ __forceinline__ unsigned long long ull_max(unsigned long long a,
                                                      unsigned long long b) {
    return a < b ? b : a;
}

// 1024 threads: 2 warps/center; each warp visits its half's 32 Morton chunks
// in ascending AABB-lower-bound order with conservative early exit.
__global__ __launch_bounds__(1024, 1)
void knn_group_kernel(const float* __restrict__ labels,
                      const float* __restrict__ inside,
                      float* __restrict__ out) {
    extern __shared__ float s[];
    float* sx = s;
    float* sy = s + Nn;
    float* sz = s + 2 * Nn;
    unsigned short* sidx = reinterpret_cast<unsigned short*>(s + 3 * Nn); // 32KB
    unsigned long long* smerge =
        reinterpret_cast<unsigned long long*>(s + 3 * Nn);  // OVERLAYS sidx
    volatile float* vth =
        reinterpret_cast<volatile float*>(s + 3 * Nn + 8192); // after 32KB

    const int b = blockIdx.y;
    const int tid = threadIdx.x;

    // Load Morton-sorted SoA + orig-idx (straight float4 copies, coalesced).
    {
        const float4* px4 = reinterpret_cast<const float4*>(g_px + b * Nn);
        const float4* py4 = reinterpret_cast<const float4*>(g_py + b * Nn);
        const float4* pz4 = reinterpret_cast<const float4*>(g_pz + b * Nn);
        float4* dx4 = reinterpret_cast<float4*>(sx);
        float4* dy4 = reinterpret_cast<float4*>(sy);
        float4* dz4 = reinterpret_cast<float4*>(sz);
        for (int i = tid; i < Nn / 4; i += 1024) {
            dx4[i] = px4[i]; dy4[i] = py4[i]; dz4[i] = pz4[i];
        }
        const float4* pi4 = reinterpret_cast<const float4*>(g_pidx + b * Nn);
        float4* di4 = reinterpret_cast<float4*>(sidx);
        for (int i = tid; i < (Nn * 2) / 16; i += 1024) di4[i] = pi4[i];
        if (tid < 32) vth[tid] = __int_as_float(0x7f800000);   // +inf
    }
    __syncthreads();

    const int wid    = tid >> 5;
    const int lane   = tid & 31;
    const int gi     = wid >> 1;
    const int parity = wid & 1;
    const int g      = blockIdx.x * 16 + gi;
    const bool active = (g < Gg);

    unsigned long long key = ~0ull;
    float cx = 0.f, cy = 0.f, cz = 0.f;

    if (active) {
        cx = g_cx[g]; cy = g_cy[g]; cz = g_cz[g];
        const float c2 = cx * cx + cy * cy + cz * cz;   // exact lattice arith

        const uint64_t cx2 = f2pack(cx, cx);
        const uint64_t cy2 = f2pack(cy, cy);
        const uint64_t cz2 = f2pack(cz, cz);
        const uint64_t c22 = f2pack(c2, c2);
        const uint64_t n22 = f2pack(-2.0f, -2.0f);

        // FROZEN precision model (verified rel_err == 0).
        auto d2exact = [&](float x, float y, float z) -> float {
            const float x2 = __fmaf_rn(z, z, __fmaf_rn(y, y, __fmul_rn(x, x)));
            const float dt = __fmaf_rn(cz, z, __fmaf_rn(cy, y, __fmul_rn(cx, x)));
            return __fsub_rn(__fadd_rn(c2, x2), __fmul_rn(2.0f, dt));
        };
        // key = d2bits(32) | origidx(16) | sortedpos(16): reference order
        // (d2 asc, orig idx asc); pos unique so extra bits never decide.
        auto mkkey = [&](float d2v, int pos) -> unsigned long long {
            unsigned uu = __float_as_uint(d2v);
            uu = (uu & 0x80000000u) ? ~uu : (uu | 0x80000000u);
            const unsigned oi = (unsigned)sidx[pos];
            return ((unsigned long long)uu << 32) | (oi << 16) | (unsigned)pos;
        };

        const int pw = wid ^ 1;   // partner warp

        // Per-lane chunk lower bound (conservative): lane i owns chunk i of
        // this warp's half.
        unsigned long long lbkey;
        {
            const int cid = parity * 32 + lane;
            const float* d = g_aabb + (b * NCH + cid) * 8;
            float dx = fmaxf(fmaxf(d[0] - cx, cx - d[1]), 0.0f);
            float dy = fmaxf(fmaxf(d[2] - cy, cy - d[3]), 0.0f);
            float dz = fmaxf(fmaxf(d[4] - cz, cz - d[5]), 0.0f);
            const float lb = __fmaf_rn(dz, dz, __fmaf_rn(dy, dy, dx * dx));
            lbkey = ((unsigned long long)__float_as_uint(lb) << 32)
                  | (unsigned)cid;
        }
        // Bitonic sort-32 ascending: visit nearest chunks first.
        #pragma unroll
        for (int k = 2; k <= 32; k <<= 1) {
            #pragma unroll
            for (int j = k >> 1; j >= 1; j >>= 1) {
                const unsigned long long o = __shfl_xor_sync(FULL, lbkey, j);
                const bool dir = ((lane & k) == 0);
                const bool keep_min = (((lane & j) == 0) == dir);
                lbkey = keep_min ? ull_min(lbkey, o) : ull_max(lbkey, o);
            }
        }

        unsigned long long thresh = ~0ull;
        float thresh_f = __int_as_float(0x7f800000);

        auto insert = [&](float d2v, int pos) {
            const unsigned long long nk = mkkey(d2v, pos);
            unsigned m = __ballot_sync(FULL, nk < thresh);
            while (m) {
                const int srcl = __ffs(m) - 1;
                m &= m - 1;
                const unsigned long long cand = __shfl_sync(FULL, nk, srcl);
                const int pos2 = __popc(__ballot_sync(FULL, key < cand));
                const unsigned long long up = __shfl_up_sync(FULL, key, 1);
                if (lane > pos2)       key = up;
                else if (lane == pos2) key = cand;
            }
        };
        auto round_refresh = [&]() {
            thresh = __shfl_sync(FULL, key, 31);
            const unsigned tu = (unsigned)(thresh >> 32);
            const unsigned ob = (tu & 0x80000000u) ? (tu ^ 0x80000000u) : ~tu;
            thresh_f = __uint_as_float(ob);
            if (lane == 0) vth[wid] = thresh_f;
        };

        auto d2pair = [&](uint64_t xp, uint64_t yp, uint64_t zp) -> uint64_t {
            const uint64_t x2 = f2fma(zp, zp, f2fma(yp, yp, f2mul(xp, xp)));
            const uint64_t dt = f2fma(cz2, zp, f2fma(cy2, yp, f2mul(cx2, xp)));
            return f2add(f2add(c22, x2), f2mul(dt, n22));
        };

        for (int j = 0; j < 32; ++j) {
            const unsigned long long v = __shfl_sync(FULL, lbkey, j);
            const int cid = (int)(v & 0xffffffffu);
            const int cbase = cid * 256;          // point base
            if (j == 0) {
                // Prefill: bitonic sort-32 of the nearest chunk's first 32.
                const int p = cbase + lane;
                key = mkkey(d2exact(sx[p], sy[p], sz[p]), p);
                #pragma unroll
                for (int k = 2; k <= 32; k <<= 1) {
                    #pragma unroll
                    for (int jj = k >> 1; jj >= 1; jj >>= 1) {
                        const unsigned long long o = __shfl_xor_sync(FULL, key, jj);
                        const bool dir = ((lane & k) == 0);
                        const bool keep_min = (((lane & jj) == 0) == dir);
                        key = keep_min ? ull_min(key, o) : ull_max(key, o);
                    }
                }
                round_refresh();
                // Mini-rounds: remaining 224 points of this chunk.
                #pragma unroll
                for (int i = 0; i < 7; ++i) {
                    const int pp = cbase + 32 + i * 32 + lane;
                    const float d2v = d2exact(sx[pp], sy[pp], sz[pp]);
                    if (__ballot_sync(FULL, d2v <= thresh_f)) {
                        insert(d2v, pp);
                        round_refresh();
                    }
                }
                continue;
            }

            const float lbj = __uint_as_float((unsigned)(v >> 32));
            const float tg = fminf(thresh_f, vth[pw]);   // partner prune
            if (lbj - LBMARGIN > tg) break;              // sorted -> all done

            // Vectorized chunk scan (256 points).
            const int j0 = cid * 64 + lane;
            const int j1 = j0 + 32;
            const ulonglong2 xa = *reinterpret_cast<const ulonglong2*>(sx + 4 * j0);
            const ulonglong2 ya = *reinterpret_cast<const ulonglong2*>(sy + 4 * j0);
            const ulonglong2 za = *reinterpret_cast<const ulonglong2*>(sz + 4 * j0);
            const ulonglong2 xb = *reinterpret_cast<const ulonglong2*>(sx + 4 * j1);
            const ulonglong2 yb = *reinterpret_cast<const ulonglong2*>(sy + 4 * j1);
            const ulonglong2 zb = *reinterpret_cast<const ulonglong2*>(sz + 4 * j1);

            const uint64_t dA = d2pair(xa.x, ya.x, za.x);
            const uint64_t dB = d2pair(xa.y, ya.y, za.y);
            const uint64_t dC = d2pair(xb.x, yb.x, zb.x);
            const uint64_t dD = d2pair(xb.y, yb.y, zb.y);

            float d0, d1, d2_, d3, d4, d5, d6, d7;
            f2unpack(dA, d0, d1);
            f2unpack(dB, d2_, d3);
            f2unpack(dC, d4, d5);
            f2unpack(dD, d6, d7);

            const float m01 = fminf(d0, d1), m23 = fminf(d2_, d3);
            const float m45 = fminf(d4, d5), m67 = fminf(d6, d7);
            const float min8 = fminf(fminf(m01, m23), fminf(m45, m67));

            if (__ballot_sync(FULL, min8 <= tg)) {
                unsigned bits = 0;
                bits |= (d0  <= tg) ? 0x01u : 0u;
                bits |= (d1  <= tg) ? 0x02u : 0u;
                bits |= (d2_ <= tg) ? 0x04u : 0u;
                bits |= (d3  <= tg) ? 0x08u : 0u;
                bits |= (d4  <= tg) ? 0x10u : 0u;
                bits |= (d5  <= tg) ? 0x20u : 0u;
                bits |= (d6  <= tg) ? 0x40u : 0u;
                bits |= (d7  <= tg) ? 0x80u : 0u;
                const unsigned am = __reduce_or_sync(FULL, bits);

                const int p0 = 4 * j0, p1 = 4 * j1;
                if (am & 0x01u) insert(d0,  p0 + 0);
                if (am & 0x02u) insert(d1,  p0 + 1);
                if (am & 0x04u) insert(d2_, p0 + 2);
                if (am & 0x08u) insert(d3,  p0 + 3);
                if (am & 0x10u) insert(d4,  p1 + 0);
                if (am & 0x20u) insert(d5,  p1 + 1);
                if (am & 0x40u) insert(d6,  p1 + 2);
                if (am & 0x80u) insert(d7,  p1 + 3);
                round_refresh();
            }
        }
    }

    __syncthreads();                       // all sidx reads done
    if (active) smerge[wid * 32 + lane] = key;   // overlays sidx region
    __syncthreads();

    if (active && (parity == 0)) {
        unsigned long long mk = ull_min(key, smerge[(wid + 1) * 32 + (31 - lane)]);
        #pragma unroll
        for (int d = 16; d >= 1; d >>= 1) {
            const unsigned long long o = __shfl_xor_sync(FULL, mk, d);
            mk = (lane & d) ? ull_max(mk, o) : ull_min(mk, o);
        }

        const int pos = (int)(mk & 0xffffu);
        const int idx = (int)((mk >> 16) & 0xffffu);   // original index
        const float px = sx[pos];
        const float py = sy[pos];
        const float pz = sz[pos];
        const int bg = b * Gg + g;

        float* o0 = out;
        float* o1 = o0 + (size_t)Bb * Gg * Kk * 3;
        float* o2 = o1 + (size_t)Bb * Gg * 3;
        float* o3 = o2 + (size_t)Bb * Gg * Kk;
        float* o4 = o3 + (size_t)Bb * Gg * Kk;

        const int r0 = (bg * Kk + lane) * 3;
        o0[r0 + 0] = __fsub_rn(px, cx);
        o0[r0 + 1] = __fsub_rn(py, cy);
        o0[r0 + 2] = __fsub_rn(pz, cz);
        if (lane == 0) {
            o1[bg * 3 + 0] = cx;
            o1[bg * 3 + 1] = cy;
            o1[bg * 3 + 2] = cz;
        }
        o2[bg * Kk + lane] = labels[b * Nn + idx];
        o3[bg * Kk + lane] = (float)idx;
        o4[bg * Kk + lane] = inside[b * Nn + idx];
    }
}

extern "C" void kernel_launch(void* const* d_in, const int* in_sizes, int n_in,
                              void* d_out, int out_size) {
    const float* xyz    = (const float*)d_in[0];
    const float* labels = (const float*)d_in[1];
    const float* inside = (const float*)d_in[2];
    float* out = (float*)d_out;

    (void)in_sizes; (void)n_in; (void)out_size;

    init_centers_kernel<<<1, 736>>>();
    morton_sort_kernel<<<Bb, 1024>>>(xyz);

    const int smem = Nn * 3 * sizeof(float)     // SoA cloud        196608
                   + Nn * sizeof(unsigned short) // sidx (∪ smerge)  32768
                   + 32 * sizeof(float);         // vth                128
    cudaFuncSetAttribute(knn_group_kernel,
                         cudaFuncAttributeMaxDynamicSharedMemorySize, smem);
    dim3 grid((Gg + 15) / 16, Bb);
    knn_group_kernel<<<grid, 1024, smem>>>(labels, inside, out);
}

// round 10
// speedup vs baseline: 2.5078x; 2.5078x over previous
#include <cuda_runtime.h>
#include <stdint.h>

#define FULL 0xffffffffu

constexpr int Bb = 8;
constexpr int Nn = 16384;
constexpr int Gg = 257;
constexpr int Kk = 32;

// Sphere-grid centers, generated at COMPILE TIME (exact lattice arithmetic,
// meshgrid('ij') order, keep iff x^2+y^2+z^2 <= 1 — equivalent to the
// verified norm <= 1+1e-6 test since the norm^2 is a multiple of 0.0625).
struct Centers { float x[Gg]; float y[Gg]; float z[Gg]; };
constexpr Centers make_centers() {
    Centers c{};
    int n = 0;
    for (int i = 0; i < 9; ++i)
        for (int j = 0; j < 9; ++j)
            for (int k = 0; k < 9; ++k) {
                const float x = -1.0f + 0.25f * (float)i;
                const float y = -1.0f + 0.25f * (float)j;
                const float z = -1.0f + 0.25f * (float)k;
                if (x * x + y * y + z * z <= 1.0f) {
                    c.x[n] = x; c.y[n] = y; c.z[n] = z; ++n;
                }
            }
    return c;
}
__constant__ Centers g_c = make_centers();

// ---- packed f32x2 exact helpers (two independent IEEE-rn fp32 lanes) ----
__device__ __forceinline__ uint64_t f2fma(uint64_t a, uint64_t b, uint64_t c) {
    uint64_t d; asm("fma.rn.f32x2 %0, %1, %2, %3;" : "=l"(d) : "l"(a), "l"(b), "l"(c));
    return d;
}
__device__ __forceinline__ uint64_t f2mul(uint64_t a, uint64_t b) {
    uint64_t d; asm("mul.rn.f32x2 %0, %1, %2;" : "=l"(d) : "l"(a), "l"(b));
    return d;
}
__device__ __forceinline__ uint64_t f2add(uint64_t a, uint64_t b) {
    uint64_t d; asm("add.rn.f32x2 %0, %1, %2;" : "=l"(d) : "l"(a), "l"(b));
    return d;
}
__device__ __forceinline__ uint64_t f2pack(float lo, float hi) {
    uint64_t d; asm("mov.b64 %0, {%1, %2};" : "=l"(d) : "f"(lo), "f"(hi));
    return d;
}
__device__ __forceinline__ void f2unpack(uint64_t v, float& lo, float& hi) {
    asm("mov.b64 {%0, %1}, %2;" : "=f"(lo), "=f"(hi) : "l"(v));
}

__device__ __forceinline__ unsigned long long ull_min(unsigned long long a,
                                                      unsigned long long b) {
    return a < b ? a : b;
}
__device__ __forceinline__ unsigned long long ull_max(unsigned long long a,
                                                      unsigned long long b) {
    return a < b ? b : a;
}

// 1024 threads: 2 warps per center, each scans half the cloud.
// Partner-threshold pruning: warp pairs share their 32nd-best via SMEM, so
// each half only retains candidates that can be in the UNION top-32 (exact).
__global__ __launch_bounds__(1024, 1)
void knn_group_kernel(const float* __restrict__ xyz,
                      const float* __restrict__ labels,
                      const float* __restrict__ inside,
                      float* __restrict__ out) {
    extern __shared__ float s[];                 // sx|sy|sz | merge | vth
    float* sx = s;
    float* sy = s + Nn;
    float* sz = s + 2 * Nn;
    unsigned long long* smerge =
        reinterpret_cast<unsigned long long*>(s + 3 * Nn);   // 32 warps * 32
    volatile float* vth =
        reinterpret_cast<volatile float*>(s + 3 * Nn + 2 * 32 * 32); // 32 floats

    const int b = blockIdx.y;
    const int tid = threadIdx.x;

    // AoS global -> SoA shared (float4 coalesced loads, scalar stores).
    {
        const float4* src = reinterpret_cast<const float4*>(xyz + (size_t)b * Nn * 3);
        for (int i = tid; i < Nn * 3 / 4; i += blockDim.x) {
            const float4 v = src[i];
            const int e = 4 * i;
            s[(e % 3) * Nn + e / 3]             = v.x;
            s[((e + 1) % 3) * Nn + (e + 1) / 3] = v.y;
            s[((e + 2) % 3) * Nn + (e + 2) / 3] = v.z;
            s[((e + 3) % 3) * Nn + (e + 3) / 3] = v.w;
        }
        if (tid < 32) vth[tid] = __int_as_float(0x7f800000);   // +inf
    }
    __syncthreads();

    const int wid    = tid >> 5;      // 0..31
    const int lane   = tid & 31;
    const int gi     = wid >> 1;      // center slot 0..15
    const int parity = wid & 1;       // which half of the cloud
    const int g      = blockIdx.x * 16 + gi;
    const bool active = (g < Gg);

    unsigned long long key = ~0ull;   // lane r = rank-r key, ascending
    float cx = 0.f, cy = 0.f, cz = 0.f;

    if (active) {
        cx = g_c.x[g]; cy = g_c.y[g]; cz = g_c.z[g];
        const float c2 = cx * cx + cy * cy + cz * cz;   // exact lattice arith

        const uint64_t cx2 = f2pack(cx, cx);
        const uint64_t cy2 = f2pack(cy, cy);
        const uint64_t cz2 = f2pack(cz, cz);
        const uint64_t c22 = f2pack(c2, c2);
        const uint64_t n22 = f2pack(-2.0f, -2.0f);

        // FROZEN scalar precision model (verified rel_err == 0):
        //   x2 = fma(z,z, fma(y,y, rn(x*x)))
        //   dt = fma(cz,z, fma(cy,y, rn(cx*x)))
        //   d2 = (c2 + x2) - rn(2*dt)
        auto d2exact = [&](float x, float y, float z) -> float {
            const float x2 = __fmaf_rn(z, z, __fmaf_rn(y, y, __fmul_rn(x, x)));
            const float dt = __fmaf_rn(cz, z, __fmaf_rn(cy, y, __fmul_rn(cx, x)));
            return __fsub_rn(__fadd_rn(c2, x2), __fmul_rn(2.0f, dt));
        };
        auto mkkey = [](float d2v, int p) -> unsigned long long {
            unsigned uu = __float_as_uint(d2v);
            uu = (uu & 0x80000000u) ? ~uu : (uu | 0x80000000u);
            return ((unsigned long long)uu << 32) | (unsigned)p;
        };

        const int half_pt = parity * (Nn / 2);      // 0 or 8192 (points)
        const int half4   = parity * (Nn / 8);      // float4 units
        const int pw      = wid ^ 1;                // partner warp

        // ---- Prefill: bitonic sort-32 of the first 32 points of the half ----
        {
            const int p = half_pt + lane;
            key = mkkey(d2exact(sx[p], sy[p], sz[p]), p);
            #pragma unroll
            for (int k = 2; k <= 32; k <<= 1) {
                #pragma unroll
                for (int j = k >> 1; j >= 1; j >>= 1) {
                    const unsigned long long o = __shfl_xor_sync(FULL, key, j);
                    const bool dir = ((lane & k) == 0);
                    const bool keep_min = (((lane & j) == 0) == dir);
                    key = keep_min ? ull_min(key, o) : ull_max(key, o);
                }
            }
        }
        unsigned long long thresh = __shfl_sync(FULL, key, 31);
        float thresh_f;
        {
            const unsigned tu = (unsigned)(thresh >> 32);
            const unsigned ob = (tu & 0x80000000u) ? (tu ^ 0x80000000u) : ~tu;
            thresh_f = __uint_as_float(ob);
        }
        if (lane == 0) vth[wid] = thresh_f;

        // Slim insert: no per-iteration staleness check or thresh reshuffle —
        // stale candidates no-op automatically (pos==32 matches no lane).
        auto insert = [&](float d2v, int p) {
            const unsigned long long nk = mkkey(d2v, p);
            unsigned m = __ballot_sync(FULL, nk < thresh);
            while (m) {
                const int srcl = __ffs(m) - 1;
                m &= m - 1;
                const unsigned long long cand = __shfl_sync(FULL, nk, srcl);
                const int pos = __popc(__ballot_sync(FULL, key < cand));
                const unsigned long long up = __shfl_up_sync(FULL, key, 1);
                if (lane > pos)       key = up;
                else if (lane == pos) key = cand;
            }
        };
        auto round_refresh = [&]() {
            thresh = __shfl_sync(FULL, key, 31);
            const unsigned tu = (unsigned)(thresh >> 32);
            const unsigned ob = (tu & 0x80000000u) ? (tu ^ 0x80000000u) : ~tu;
            thresh_f = __uint_as_float(ob);
            if (lane == 0) vth[wid] = thresh_f;
        };

        // ---- Mini-rounds: points 32..255 of the half (7 x 32, scalar) ----
        #pragma unroll
        for (int i = 0; i < 7; ++i) {
            const int p = half_pt + 32 + i * 32 + lane;
            const float d2v = d2exact(sx[p], sy[p], sz[p]);
            const float tg = fminf(thresh_f, vth[pw]);   // partner prune
            if (__ballot_sync(FULL, d2v <= tg)) {
                insert(d2v, p);
                round_refresh();
            }
        }

        // ---- Full rounds: points 256..8191 of the half (31 x 256) ----
        auto d2pair = [&](uint64_t xp, uint64_t yp, uint64_t zp) -> uint64_t {
            const uint64_t x2 = f2fma(zp, zp, f2fma(yp, yp, f2mul(xp, xp)));
            const uint64_t dt = f2fma(cz2, zp, f2fma(cy2, yp, f2mul(cx2, xp)));
            return f2add(f2add(c22, x2), f2mul(dt, n22));
        };

        for (int it = 1; it < 32; ++it) {
            const int j0 = half4 + it * 64 + lane;
            const int j1 = j0 + 32;

            const ulonglong2 xa = *reinterpret_cast<const ulonglong2*>(sx + 4 * j0);
            const ulonglong2 ya = *reinterpret_cast<const ulonglong2*>(sy + 4 * j0);
            const ulonglong2 za = *reinterpret_cast<const ulonglong2*>(sz + 4 * j0);
            const ulonglong2 xb = *reinterpret_cast<const ulonglong2*>(sx + 4 * j1);
            const ulonglong2 yb = *reinterpret_cast<const ulonglong2*>(sy + 4 * j1);
            const ulonglong2 zb = *reinterpret_cast<const ulonglong2*>(sz + 4 * j1);

            const uint64_t dA = d2pair(xa.x, ya.x, za.x);   // pts 4j0+0,1
            const uint64_t dB = d2pair(xa.y, ya.y, za.y);   // pts 4j0+2,3
            const uint64_t dC = d2pair(xb.x, yb.x, zb.x);   // pts 4j1+0,1
            const uint64_t dD = d2pair(xb.y, yb.y, zb.y);   // pts 4j1+2,3

            float d0, d1, d2_, d3, d4, d5, d6, d7;
            f2unpack(dA, d0, d1);
            f2unpack(dB, d2_, d3);
            f2unpack(dC, d4, d5);
            f2unpack(dD, d6, d7);

            const float m01 = fminf(d0, d1), m23 = fminf(d2_, d3);
            const float m45 = fminf(d4, d5), m67 = fminf(d6, d7);
            const float min8 = fminf(fminf(m01, m23), fminf(m45, m67));

            const float tg = fminf(thresh_f, vth[pw]);   // partner prune

            if (__ballot_sync(FULL, min8 <= tg)) {
                unsigned bits = 0;
                bits |= (d0  <= tg) ? 0x01u : 0u;
                bits |= (d1  <= tg) ? 0x02u : 0u;
                bits |= (d2_ <= tg) ? 0x04u : 0u;
                bits |= (d3  <= tg) ? 0x08u : 0u;
                bits |= (d4  <= tg) ? 0x10u : 0u;
                bits |= (d5  <= tg) ? 0x20u : 0u;
                bits |= (d6  <= tg) ? 0x40u : 0u;
                bits |= (d7  <= tg) ? 0x80u : 0u;
                const unsigned am = __reduce_or_sync(FULL, bits);  // uniform

                const int p0 = 4 * j0, p1 = 4 * j1;
                if (am & 0x01u) insert(d0,  p0 + 0);
                if (am & 0x02u) insert(d1,  p0 + 1);
                if (am & 0x04u) insert(d2_, p0 + 2);
                if (am & 0x08u) insert(d3,  p0 + 3);
                if (am & 0x10u) insert(d4,  p1 + 0);
                if (am & 0x20u) insert(d5,  p1 + 1);
                if (am & 0x40u) insert(d6,  p1 + 2);
                if (am & 0x80u) insert(d7,  p1 + 3);
                round_refresh();
            }
        }
    }

    // Pair-merge: warps (2i, 2i+1) hold (pruned) top-32 lists whose union
    // provably contains the exact union top-32.
    if (active) smerge[wid * 32 + lane] = key;
    __syncthreads();

    if (active && (parity == 0)) {
        // min(A[r], B[31-r]) = lowest-32 of the union (bitonic); then sort.
        unsigned long long mk = ull_min(key, smerge[(wid + 1) * 32 + (31 - lane)]);
        #pragma unroll
        for (int d = 16; d >= 1; d >>= 1) {
            const unsigned long long o = __shfl_xor_sync(FULL, mk, d);
            mk = (lane & d) ? ull_max(mk, o) : ull_min(mk, o);
        }

        const int idx = (int)(mk & 0xffffffffu);
        const float px = sx[idx];
        const float py = sy[idx];
        const float pz = sz[idx];
        const int bg = b * Gg + g;

        float* o0 = out;                                   // neigh [B,G,32,3]
        float* o1 = o0 + (size_t)Bb * Gg * Kk * 3;         // center [B,G,3]
        float* o2 = o1 + (size_t)Bb * Gg * 3;              // labels [B,G,32,1]
        float* o3 = o2 + (size_t)Bb * Gg * Kk;             // idx    [B,G,32]
        float* o4 = o3 + (size_t)Bb * Gg * Kk;             // inside [B,G,32,1]

        const int r0 = (bg * Kk + lane) * 3;
        o0[r0 + 0] = __fsub_rn(px, cx);
        o0[r0 + 1] = __fsub_rn(py, cy);
        o0[r0 + 2] = __fsub_rn(pz, cz);
        if (lane == 0) {
            o1[bg * 3 + 0] = cx;
            o1[bg * 3 + 1] = cy;
            o1[bg * 3 + 2] = cz;
        }
        o2[bg * Kk + lane] = labels[b * Nn + idx];
        o3[bg * Kk + lane] = (float)idx;
        o4[bg * Kk + lane] = inside[b * Nn + idx];
    }
}

extern "C" void kernel_launch(void* const* d_in, const int* in_sizes, int n_in,
                              void* d_out, int out_size) {
    const float* xyz    = (const float*)d_in[0];
    const float* labels = (const float*)d_in[1];
    const float* inside = (const float*)d_in[2];
    float* out = (float*)d_out;

    (void)in_sizes; (void)n_in; (void)out_size;

    const int smem = Nn * 3 * sizeof(float)
                   + 32 * 32 * sizeof(unsigned long long)
                   + 32 * sizeof(float);
    cudaFuncSetAttribute(knn_group_kernel,
                         cudaFuncAttributeMaxDynamicSharedMemorySize, smem);
    dim3 grid((Gg + 15) / 16, Bb);
    knn_group_kernel<<<grid, 1024, smem>>>(xyz, labels, inside, out);
}